// round 5
// baseline (speedup 1.0000x reference)
#include <cuda_runtime.h>

// DeformConv: B=8, C=64, H=W=96, COUT=64, 3x3, stride=1, pad=1, dil=1
// out[b,o,h,w] = sum_{c,k} weight[o,c,k] * bilinear(x[b,c], p(k,h,w) + offset[b,k,:,h,w])

#define B_    8
#define C_    64
#define H_    96
#define W_    96
#define CO_   64
#define K2_   9
#define NPIX  (H_ * W_)      // 9216
#define TILE  64             // output pixels per block
#define NTHREADS 256

// Pre-transposed weight: wT[k][c][o] = weight[o][c][k]  (147 KB scratch)
__device__ __align__(16) float g_wT[K2_ * C_ * CO_];

__global__ void wtrans_kernel(const float* __restrict__ w) {
    int idx = blockIdx.x * 256 + threadIdx.x;           // 0 .. 36863
    if (idx >= CO_ * C_ * K2_) return;
    int o   = idx / (C_ * K2_);
    int rem = idx % (C_ * K2_);
    int c   = rem / K2_;
    int k   = rem % K2_;
    g_wT[(k * C_ + c) * CO_ + o] = w[idx];
}

// ---- f32x2 packed math (2 fp32 FMAs per instruction) ----
__device__ __forceinline__ unsigned long long pack2(float a, float b) {
    unsigned long long r;
    asm("mov.b64 %0, {%1, %2};" : "=l"(r) : "f"(a), "f"(b));
    return r;
}
__device__ __forceinline__ void fma2(unsigned long long& d,
                                     unsigned long long a,
                                     unsigned long long b) {
    asm("fma.rn.f32x2 %0, %1, %2, %0;" : "+l"(d) : "l"(a), "l"(b));
}
__device__ __forceinline__ void unpack2(unsigned long long v, float& a, float& b) {
    asm("mov.b64 {%0, %1}, %2;" : "=f"(a), "=f"(b) : "l"(v));
}

__global__ __launch_bounds__(NTHREADS) void dconv_kernel(
    const float* __restrict__ x,
    const float* __restrict__ off,
    float* __restrict__ out)
{
    __shared__ __align__(16) float cols[C_][TILE];   // 16 KB: column tile for current tap
    __shared__ __align__(16) float wsm[C_][CO_];     // 16 KB: weight slice wsm[c][o]
    __shared__ int   s_o0[TILE], s_o1[TILE], s_o2[TILE], s_o3[TILE];
    __shared__ float s_w0[TILE], s_w1[TILE], s_w2[TILE], s_w3[TILE];

    const int t = threadIdx.x;
    const int b = blockIdx.y;
    const int tile_base = blockIdx.x * TILE;

    // GEMM micro-tile assignment: 16 px-groups x 16 o-groups
    const int tx = t & 15;    // pixels tx*4 .. tx*4+3
    const int ty = t >> 4;    // outputs ty*4 .. ty*4+3

    unsigned long long acc[4][2];
#pragma unroll
    for (int i = 0; i < 4; i++) { acc[i][0] = 0ull; acc[i][1] = 0ull; }

    const float* xb = x + (size_t)b * C_ * NPIX;

    for (int k = 0; k < K2_; k++) {
        __syncthreads();   // protect cols/wsm/coord arrays from previous iteration's readers

        // --- stage weight slice for this tap (coalesced float4) ---
        {
            const float4* wk = (const float4*)(g_wT + k * C_ * CO_);
            float4* wd = (float4*)&wsm[0][0];
#pragma unroll
            for (int i = 0; i < 4; i++)
                wd[t + NTHREADS * i] = wk[t + NTHREADS * i];
        }

        // --- per-pixel bilinear coordinates for this tap ---
        if (t < TILE) {
            int p  = tile_base + t;
            int ho = p / W_;
            int wo = p % W_;
            float offy = off[((size_t)b * (2 * K2_) + 2 * k    ) * NPIX + p];
            float offx = off[((size_t)b * (2 * K2_) + 2 * k + 1) * NPIX + p];
            float py = (float)(ho - 1 + k / 3) + offy;
            float px = (float)(wo - 1 + k % 3) + offx;
            float y0f = floorf(py), x0f = floorf(px);
            float ly = py - y0f,    lx = px - x0f;
            int y0 = (int)y0f, x0 = (int)x0f;
            int y1 = y0 + 1,   x1 = x0 + 1;
            float vy0 = (y0 >= 0 && y0 < H_) ? 1.f : 0.f;
            float vy1 = (y1 >= 0 && y1 < H_) ? 1.f : 0.f;
            float vx0 = (x0 >= 0 && x0 < W_) ? 1.f : 0.f;
            float vx1 = (x1 >= 0 && x1 < W_) ? 1.f : 0.f;
            int y0c = min(max(y0, 0), H_ - 1), y1c = min(max(y1, 0), H_ - 1);
            int x0c = min(max(x0, 0), W_ - 1), x1c = min(max(x1, 0), W_ - 1);
            s_o0[t] = y0c * W_ + x0c;  s_w0[t] = (1.f - ly) * (1.f - lx) * vy0 * vx0;
            s_o1[t] = y0c * W_ + x1c;  s_w1[t] = (1.f - ly) * lx         * vy0 * vx1;
            s_o2[t] = y1c * W_ + x0c;  s_w2[t] = ly         * (1.f - lx) * vy1 * vx0;
            s_o3[t] = y1c * W_ + x1c;  s_w3[t] = ly         * lx         * vy1 * vx1;
        }
        __syncthreads();

        // --- gather column tile: cols[c][p] (coords cached in regs across c) ---
        {
            const int p  = t & 63;
            const int cg = t >> 6;   // 0..3 -> channels cg*16 .. cg*16+15
            const int o0 = s_o0[p], o1 = s_o1[p], o2 = s_o2[p], o3 = s_o3[p];
            const float w0 = s_w0[p], w1 = s_w1[p], w2 = s_w2[p], w3 = s_w3[p];
            const float* xc = xb + (size_t)(cg * 16) * NPIX;
#pragma unroll
            for (int i = 0; i < 16; i++) {
                float v = w0 * __ldg(xc + o0) + w1 * __ldg(xc + o1)
                        + w2 * __ldg(xc + o2) + w3 * __ldg(xc + o3);
                cols[cg * 16 + i][p] = v;
                xc += NPIX;
            }
        }
        __syncthreads();

        // --- GEMM step: acc[o][p] += wsm[c][o] * cols[c][p], c = 0..63 ---
#pragma unroll 16
        for (int r = 0; r < C_; r++) {
            float4 c4 = *(const float4*)&cols[r][tx * 4];
            float4 w4 = *(const float4*)&wsm[r][ty * 4];
            unsigned long long c01 = pack2(c4.x, c4.y);
            unsigned long long c23 = pack2(c4.z, c4.w);
            unsigned long long wp;
            wp = pack2(w4.x, w4.x); fma2(acc[0][0], wp, c01); fma2(acc[0][1], wp, c23);
            wp = pack2(w4.y, w4.y); fma2(acc[1][0], wp, c01); fma2(acc[1][1], wp, c23);
            wp = pack2(w4.z, w4.z); fma2(acc[2][0], wp, c01); fma2(acc[2][1], wp, c23);
            wp = pack2(w4.w, w4.w); fma2(acc[3][0], wp, c01); fma2(acc[3][1], wp, c23);
        }
    }

    // --- epilogue: float4 stores, fully coalesced along pixel dim ---
#pragma unroll
    for (int oi = 0; oi < 4; oi++) {
        int o = ty * 4 + oi;
        float4 v;
        unpack2(acc[oi][0], v.x, v.y);
        unpack2(acc[oi][1], v.z, v.w);
        *(float4*)(out + ((size_t)(b * CO_ + o)) * NPIX + tile_base + tx * 4) = v;
    }
}

extern "C" void kernel_launch(void* const* d_in, const int* in_sizes, int n_in,
                              void* d_out, int out_size) {
    const float* x   = (const float*)d_in[0];   // (8, 64, 96, 96)
    const float* off = (const float*)d_in[1];   // (8, 18, 96, 96)
    const float* w   = (const float*)d_in[2];   // (64, 64, 3, 3)
    float* out = (float*)d_out;                 // (8, 64, 96, 96)

    wtrans_kernel<<<(CO_ * C_ * K2_ + 255) / 256, 256>>>(w);

    dim3 grid(NPIX / TILE, B_);                 // (144, 8) = 1152 blocks
    dconv_kernel<<<grid, NTHREADS>>>(x, off, out);
}

// round 9
// speedup vs baseline: 1.1091x; 1.1091x over previous
#include <cuda_runtime.h>

// DeformConv: B=8, C=64, H=W=96, COUT=64, 3x3, stride=1, pad=1, dil=1
// Strategy: channel-last transpose of x -> coalesced bilinear gather,
//           128px x 64o tile GEMM with 8x8 micro-tile in f32x2,
//           XOR-swizzled cols smem (conflict-free STS and LDS),
//           weights pre-duplicated for direct f32x2 splat loads.
// R8 fix: weight row stride is 32 ulonglong2 (128 floats), not 16.

#define B_    8
#define C_    64
#define H_    96
#define W_    96
#define CO_   64
#define K2_   9
#define NPIX  (H_ * W_)      // 9216
#define TILE  128            // output pixels per block
#define NTHR  128

// [k][c][o*2 dup]  (9*64*128 floats = 288 KB)
__device__ __align__(16) float g_wT[K2_ * C_ * 128];
// [b][p][c] channel-last x  (18.9 MB)
__device__ __align__(16) float g_xT[B_ * NPIX * C_];

__global__ void wtrans_kernel(const float* __restrict__ w) {
    int idx = blockIdx.x * 256 + threadIdx.x;           // o*576 + c*9 + k
    if (idx >= CO_ * C_ * K2_) return;
    int o   = idx / (C_ * K2_);
    int rem = idx % (C_ * K2_);
    int c   = rem / K2_;
    int k   = rem % K2_;
    float v = w[idx];
    float* dst = g_wT + (k * C_ + c) * 128 + o * 2;
    dst[0] = v;          // duplicated pair -> direct f32x2 splat
    dst[1] = v;
}

// x[b][c][p] -> g_xT[b][p][c], 32x32 smem-tiled transpose
__global__ void xtrans_kernel(const float* __restrict__ x) {
    __shared__ float tl[32][33];
    int b  = blockIdx.z;
    int c0 = blockIdx.y * 32;
    int p0 = blockIdx.x * 32;
    int lane = threadIdx.x & 31;
    int wrp  = threadIdx.x >> 5;    // 0..7
#pragma unroll
    for (int i = 0; i < 4; i++) {
        int cr = wrp * 4 + i;
        tl[cr][lane] = x[((size_t)b * C_ + c0 + cr) * NPIX + p0 + lane];
    }
    __syncthreads();
#pragma unroll
    for (int i = 0; i < 4; i++) {
        int pr = wrp * 4 + i;
        g_xT[((size_t)b * NPIX + p0 + pr) * C_ + c0 + lane] = tl[lane][pr];
    }
}

// ---- f32x2 packed math ----
__device__ __forceinline__ void fma2(unsigned long long& d,
                                     unsigned long long a,
                                     unsigned long long b) {
    asm("fma.rn.f32x2 %0, %1, %2, %0;" : "+l"(d) : "l"(a), "l"(b));
}
__device__ __forceinline__ void unpack2(unsigned long long v, float& a, float& b) {
    asm("mov.b64 {%0, %1}, %2;" : "=f"(a), "=f"(b) : "l"(v));
}

__global__ __launch_bounds__(NTHR) void dconv_kernel(
    const float* __restrict__ off,
    float* __restrict__ out)
{
    // cols[c][px] with XOR swizzle: word = c*128 + (px ^ 4*((c>>3)&7))
    __shared__ __align__(16) float cols[C_ * TILE];   // 32 KB
    __shared__ int2   s_idx[TILE];                     // (o_top, o_bot) element offsets
    __shared__ float4 s_cf[TILE];                      // folded bilinear coefficients

    const int t = threadIdx.x;
    const int b = blockIdx.y;
    const int tile_base = blockIdx.x * TILE;

    // GEMM micro-tile: tx -> pixels {tx*4..+3} and {64+tx*4..+3}; ty -> outputs ty*8..+7
    const int tx = t & 15;
    const int ty = t >> 4;

    // gather mapping: 8 channel-groups x 16 pixel-groups
    const int sthr = t & 7;          // channel group: c = sthr*8 .. +7
    const int pg   = t >> 3;         // pixel group base

    // per-thread pixel constants for coordinate stage (px = t)
    const int p  = tile_base + t;
    const int ho = p / W_;
    const int wo = p - ho * W_;

    unsigned long long acc[32];
#pragma unroll
    for (int i = 0; i < 32; i++) acc[i] = 0ull;

    const float* xb = g_xT + (size_t)b * (NPIX * C_);

    for (int k = 0; k < K2_; k++) {
        __syncthreads();   // previous GEMM done reading cols; coords consumed

        // ---- per-pixel coords + folded coefficients (px = t) ----
        {
            float offy = off[((size_t)b * (2 * K2_) + 2 * k    ) * NPIX + p];
            float offx = off[((size_t)b * (2 * K2_) + 2 * k + 1) * NPIX + p];
            float py  = (float)(ho - 1 + k / 3) + offy;
            float pxf = (float)(wo - 1 + k % 3) + offx;
            float y0f = floorf(py), x0f = floorf(pxf);
            float ly = py - y0f,    lx = pxf - x0f;
            int y0 = (int)y0f, x0 = (int)x0f;
            int y1 = y0 + 1,   x1 = x0 + 1;
            float vy0 = (y0 >= 0 && y0 < H_) ? 1.f : 0.f;
            float vy1 = (y1 >= 0 && y1 < H_) ? 1.f : 0.f;
            float vx0 = (x0 >= 0 && x0 < W_) ? 1.f : 0.f;
            float vx1 = (x1 >= 0 && x1 < W_) ? 1.f : 0.f;
            float w00 = (1.f - ly) * (1.f - lx) * vy0 * vx0;
            float w01 = (1.f - ly) * lx         * vy0 * vx1;
            float w10 = ly         * (1.f - lx) * vy1 * vx0;
            float w11 = ly         * lx         * vy1 * vx1;
            int xl = min(max(x0, 0), W_ - 2);
            float s0  = (x0 == xl)     ? 1.f : 0.f;   // column xl carries corner x0
            float s1  = (x1 == xl)     ? 1.f : 0.f;   // column xl carries corner x1 (left clamp)
            float s0p = (x0 == xl + 1) ? 1.f : 0.f;   // column xl+1 carries corner x0 (right clamp)
            float ca = s0  * w00 + s1 * w01;          // coeff of (y0 row, col xl)
            float cb = s0p * w00 + s0 * w01;          // coeff of (y0 row, col xl+1)
            float cc = s0  * w10 + s1 * w11;          // coeff of (y1 row, col xl)
            float cd = s0p * w10 + s0 * w11;          // coeff of (y1 row, col xl+1)
            int y0c = min(max(y0, 0), H_ - 1);
            int y1c = min(max(y1, 0), H_ - 1);
            s_idx[t] = make_int2((y0c * W_ + xl) * C_, (y1c * W_ + xl) * C_);
            s_cf[t]  = make_float4(ca, cb, cc, cd);
        }
        __syncthreads();

        // ---- gather: fully coalesced LDG.128 from channel-last xT ----
        {
            const int c0 = sthr * 8;
            const int swx = sthr * 4;
#pragma unroll 2
            for (int i = 0; i < 8; i++) {
                int pxi = pg + i * 16;
                int2   oo = s_idx[pxi];
                float4 cf = s_cf[pxi];
                const float4* A  = (const float4*)(xb + oo.x + c0);       // (y0, xl)
                const float4* Bp = (const float4*)(xb + oo.x + C_ + c0);  // (y0, xl+1)
                const float4* Cp = (const float4*)(xb + oo.y + c0);       // (y1, xl)
                const float4* Dp = (const float4*)(xb + oo.y + C_ + c0);  // (y1, xl+1)
                float* dst = &cols[c0 * TILE + (pxi ^ swx)];
                float4 va = A[0], vb = Bp[0], vc = Cp[0], vd = Dp[0];
                dst[0 * TILE] = cf.x * va.x + cf.y * vb.x + cf.z * vc.x + cf.w * vd.x;
                dst[1 * TILE] = cf.x * va.y + cf.y * vb.y + cf.z * vc.y + cf.w * vd.y;
                dst[2 * TILE] = cf.x * va.z + cf.y * vb.z + cf.z * vc.z + cf.w * vd.z;
                dst[3 * TILE] = cf.x * va.w + cf.y * vb.w + cf.z * vc.w + cf.w * vd.w;
                va = A[1]; vb = Bp[1]; vc = Cp[1]; vd = Dp[1];
                dst[4 * TILE] = cf.x * va.x + cf.y * vb.x + cf.z * vc.x + cf.w * vd.x;
                dst[5 * TILE] = cf.x * va.y + cf.y * vb.y + cf.z * vc.y + cf.w * vd.y;
                dst[6 * TILE] = cf.x * va.z + cf.y * vb.z + cf.z * vc.z + cf.w * vd.z;
                dst[7 * TILE] = cf.x * va.w + cf.y * vb.w + cf.z * vc.w + cf.w * vd.w;
            }
        }
        __syncthreads();

        // ---- GEMM step: acc[o][px] += w[o][c] * cols[c][px], c = 0..63 ----
        {
            const ulonglong2* cols16 = (const ulonglong2*)cols;
            const ulonglong2* wbase  = (const ulonglong2*)(g_wT + k * (C_ * 128));
#pragma unroll 2
            for (int rg = 0; rg < 8; rg++) {
                const ulonglong2* cA = cols16 + rg * 8 * 32 + (tx ^ rg);
                // FIX: each (k,c) weight row = 128 floats = 32 ulonglong2
                const ulonglong2* wp = wbase + rg * 8 * 32 + ty * 4;
#pragma unroll
                for (int j = 0; j < 8; j++) {
                    ulonglong2 a   = cA[0];    // A01, A23 (pixels 4tx..4tx+3)
                    ulonglong2 bql = cA[16];   // B01, B23 (pixels 64+4tx..+3)
                    ulonglong2 w01 = __ldg(wp);
                    ulonglong2 w23 = __ldg(wp + 1);
                    ulonglong2 w45 = __ldg(wp + 2);
                    ulonglong2 w67 = __ldg(wp + 3);
                    fma2(acc[ 0], w01.x, a.x);   fma2(acc[ 1], w01.x, a.y);
                    fma2(acc[ 2], w01.x, bql.x); fma2(acc[ 3], w01.x, bql.y);
                    fma2(acc[ 4], w01.y, a.x);   fma2(acc[ 5], w01.y, a.y);
                    fma2(acc[ 6], w01.y, bql.x); fma2(acc[ 7], w01.y, bql.y);
                    fma2(acc[ 8], w23.x, a.x);   fma2(acc[ 9], w23.x, a.y);
                    fma2(acc[10], w23.x, bql.x); fma2(acc[11], w23.x, bql.y);
                    fma2(acc[12], w23.y, a.x);   fma2(acc[13], w23.y, a.y);
                    fma2(acc[14], w23.y, bql.x); fma2(acc[15], w23.y, bql.y);
                    fma2(acc[16], w45.x, a.x);   fma2(acc[17], w45.x, a.y);
                    fma2(acc[18], w45.x, bql.x); fma2(acc[19], w45.x, bql.y);
                    fma2(acc[20], w45.y, a.x);   fma2(acc[21], w45.y, a.y);
                    fma2(acc[22], w45.y, bql.x); fma2(acc[23], w45.y, bql.y);
                    fma2(acc[24], w67.x, a.x);   fma2(acc[25], w67.x, a.y);
                    fma2(acc[26], w67.x, bql.x); fma2(acc[27], w67.x, bql.y);
                    fma2(acc[28], w67.y, a.x);   fma2(acc[29], w67.y, a.y);
                    fma2(acc[30], w67.y, bql.x); fma2(acc[31], w67.y, bql.y);
                    cA += 32;
                    wp += 32;   // FIX: advance one full 128-float row per channel
                }
            }
        }
    }

    // ---- epilogue: float4 stores, coalesced along pixel dim ----
#pragma unroll
    for (int oi = 0; oi < 8; oi++) {
        int o = ty * 8 + oi;
        float* obase = out + ((size_t)(b * CO_ + o)) * NPIX + tile_base;
        float4 vA, vB;
        unpack2(acc[oi * 4 + 0], vA.x, vA.y);
        unpack2(acc[oi * 4 + 1], vA.z, vA.w);
        unpack2(acc[oi * 4 + 2], vB.x, vB.y);
        unpack2(acc[oi * 4 + 3], vB.z, vB.w);
        *(float4*)(obase + tx * 4)      = vA;
        *(float4*)(obase + 64 + tx * 4) = vB;
    }
}

extern "C" void kernel_launch(void* const* d_in, const int* in_sizes, int n_in,
                              void* d_out, int out_size) {
    const float* x   = (const float*)d_in[0];   // (8, 64, 96, 96)
    const float* off = (const float*)d_in[1];   // (8, 18, 96, 96)
    const float* w   = (const float*)d_in[2];   // (64, 64, 3, 3)
    float* out = (float*)d_out;                 // (8, 64, 96, 96)

    wtrans_kernel<<<(CO_ * C_ * K2_ + 255) / 256, 256>>>(w);

    dim3 tgrid(NPIX / 32, C_ / 32, B_);         // (288, 2, 8)
    xtrans_kernel<<<tgrid, 256>>>(x);

    dim3 grid(NPIX / TILE, B_);                 // (72, 8) = 576 blocks
    dconv_kernel<<<grid, NTHR>>>(off, out);
}

// round 10
// speedup vs baseline: 2.1745x; 1.9606x over previous
#include <cuda_runtime.h>

// DeformConv: B=8, C=64, H=W=96, COUT=64, 3x3, stride=1, pad=1, dil=1
// R10: weights moved to smem (staged per tap), f32x2 splat via mov.b64,
//      occupancy pinned at 4 blocks/SM (51KB dynamic smem, 128-reg cap)
//      -> single well-packed wave, LSU pressure cut ~6x.

#define B_    8
#define C_    64
#define H_    96
#define W_    96
#define CO_   64
#define K2_   9
#define NPIX  (H_ * W_)      // 9216
#define TILE  128            // output pixels per block
#define NTHR  128

// dynamic smem partition (bytes)
//   cols : 64*128*4  = 32768
//   wsm  : 64*64*4   = 16384
//   s_idx: 128*8     = 1024
//   s_cf : 128*16    = 2048
#define SMEM_BYTES (32768 + 16384 + 1024 + 2048)

// [k][c][o] plain transposed weight (144 KB)
__device__ __align__(16) float g_w2[K2_ * C_ * CO_];
// [b][p][c] channel-last x  (18.9 MB)
__device__ __align__(16) float g_xT[B_ * NPIX * C_];

__global__ void wtrans_kernel(const float* __restrict__ w) {
    int idx = blockIdx.x * 256 + threadIdx.x;           // o*576 + c*9 + k
    if (idx >= CO_ * C_ * K2_) return;
    int o   = idx / (C_ * K2_);
    int rem = idx % (C_ * K2_);
    int c   = rem / K2_;
    int k   = rem % K2_;
    g_w2[(k * C_ + c) * CO_ + o] = w[idx];
}

// x[b][c][p] -> g_xT[b][p][c], 32x32 smem-tiled transpose
__global__ void xtrans_kernel(const float* __restrict__ x) {
    __shared__ float tl[32][33];
    int b  = blockIdx.z;
    int c0 = blockIdx.y * 32;
    int p0 = blockIdx.x * 32;
    int lane = threadIdx.x & 31;
    int wrp  = threadIdx.x >> 5;    // 0..7
#pragma unroll
    for (int i = 0; i < 4; i++) {
        int cr = wrp * 4 + i;
        tl[cr][lane] = x[((size_t)b * C_ + c0 + cr) * NPIX + p0 + lane];
    }
    __syncthreads();
#pragma unroll
    for (int i = 0; i < 4; i++) {
        int pr = wrp * 4 + i;
        g_xT[((size_t)b * NPIX + p0 + pr) * C_ + c0 + lane] = tl[lane][pr];
    }
}

// ---- f32x2 packed math ----
__device__ __forceinline__ void fma2(unsigned long long& d,
                                     unsigned long long a,
                                     unsigned long long b) {
    asm("fma.rn.f32x2 %0, %1, %2, %0;" : "+l"(d) : "l"(a), "l"(b));
}
__device__ __forceinline__ unsigned long long splat2(float v) {
    unsigned long long r;
    asm("mov.b64 %0, {%1, %1};" : "=l"(r) : "f"(v));
    return r;
}
__device__ __forceinline__ void unpack2(unsigned long long v, float& a, float& b) {
    asm("mov.b64 {%0, %1}, %2;" : "=f"(a), "=f"(b) : "l"(v));
}

__global__ __launch_bounds__(NTHR, 4) void dconv_kernel(
    const float* __restrict__ off,
    float* __restrict__ out)
{
    extern __shared__ __align__(16) char smraw[];
    float* cols  = (float*)smraw;                         // [C_ * TILE], XOR-swizzled
    float* wsm   = cols + C_ * TILE;                      // [C_ * CO_]  wsm[c*64+o]
    int2*  s_idx = (int2*)(wsm + C_ * CO_);               // [TILE]
    float4* s_cf = (float4*)(s_idx + TILE);               // [TILE]

    const int t = threadIdx.x;
    const int b = blockIdx.y;
    const int tile_base = blockIdx.x * TILE;

    // GEMM micro-tile: tx -> pixels {tx*4..+3} and {64+tx*4..+3}; ty -> outputs ty*8..+7
    const int tx = t & 15;
    const int ty = t >> 4;

    // gather mapping: 8 channel-groups x 16 pixel-groups
    const int sthr = t & 7;          // channel group: c = sthr*8 .. +7
    const int pg   = t >> 3;         // pixel group base

    // per-thread pixel constants for coordinate stage (px = t)
    const int p  = tile_base + t;
    const int ho = p / W_;
    const int wo = p - ho * W_;

    unsigned long long acc[32];
#pragma unroll
    for (int i = 0; i < 32; i++) acc[i] = 0ull;

    const float* xb = g_xT + (size_t)b * (NPIX * C_);

    for (int k = 0; k < K2_; k++) {
        __syncthreads();   // prev GEMM done reading cols/wsm; coords consumed

        // ---- stage weight tap slice into smem (16 KB, coalesced) ----
        {
            const float4* src = (const float4*)(g_w2 + k * (C_ * CO_));
            float4* dst4 = (float4*)wsm;
#pragma unroll
            for (int i = 0; i < 8; i++)
                dst4[t + NTHR * i] = __ldg(src + t + NTHR * i);
        }

        // ---- per-pixel coords + folded coefficients (px = t) ----
        {
            float offy = off[((size_t)b * (2 * K2_) + 2 * k    ) * NPIX + p];
            float offx = off[((size_t)b * (2 * K2_) + 2 * k + 1) * NPIX + p];
            float py  = (float)(ho - 1 + k / 3) + offy;
            float pxf = (float)(wo - 1 + k % 3) + offx;
            float y0f = floorf(py), x0f = floorf(pxf);
            float ly = py - y0f,    lx = pxf - x0f;
            int y0 = (int)y0f, x0 = (int)x0f;
            int y1 = y0 + 1,   x1 = x0 + 1;
            float vy0 = (y0 >= 0 && y0 < H_) ? 1.f : 0.f;
            float vy1 = (y1 >= 0 && y1 < H_) ? 1.f : 0.f;
            float vx0 = (x0 >= 0 && x0 < W_) ? 1.f : 0.f;
            float vx1 = (x1 >= 0 && x1 < W_) ? 1.f : 0.f;
            float w00 = (1.f - ly) * (1.f - lx) * vy0 * vx0;
            float w01 = (1.f - ly) * lx         * vy0 * vx1;
            float w10 = ly         * (1.f - lx) * vy1 * vx0;
            float w11 = ly         * lx         * vy1 * vx1;
            int xl = min(max(x0, 0), W_ - 2);
            float s0  = (x0 == xl)     ? 1.f : 0.f;   // column xl carries corner x0
            float s1  = (x1 == xl)     ? 1.f : 0.f;   // column xl carries corner x1 (left clamp)
            float s0p = (x0 == xl + 1) ? 1.f : 0.f;   // column xl+1 carries corner x0 (right clamp)
            float ca = s0  * w00 + s1 * w01;          // coeff of (y0 row, col xl)
            float cb = s0p * w00 + s0 * w01;          // coeff of (y0 row, col xl+1)
            float cc = s0  * w10 + s1 * w11;          // coeff of (y1 row, col xl)
            float cd = s0p * w10 + s0 * w11;          // coeff of (y1 row, col xl+1)
            int y0c = min(max(y0, 0), H_ - 1);
            int y1c = min(max(y1, 0), H_ - 1);
            s_idx[t] = make_int2((y0c * W_ + xl) * C_, (y1c * W_ + xl) * C_);
            s_cf[t]  = make_float4(ca, cb, cc, cd);
        }
        __syncthreads();

        // ---- gather: fully coalesced LDG.128 from channel-last xT ----
        {
            const int c0 = sthr * 8;
            const int swx = sthr * 4;
#pragma unroll 2
            for (int i = 0; i < 8; i++) {
                int pxi = pg + i * 16;
                int2   oo = s_idx[pxi];
                float4 cf = s_cf[pxi];
                const float4* A  = (const float4*)(xb + oo.x + c0);       // (y0, xl)
                const float4* Bp = (const float4*)(xb + oo.x + C_ + c0);  // (y0, xl+1)
                const float4* Cp = (const float4*)(xb + oo.y + c0);       // (y1, xl)
                const float4* Dp = (const float4*)(xb + oo.y + C_ + c0);  // (y1, xl+1)
                float* dst = &cols[c0 * TILE + (pxi ^ swx)];
                float4 va = A[0], vb = Bp[0], vc = Cp[0], vd = Dp[0];
                dst[0 * TILE] = cf.x * va.x + cf.y * vb.x + cf.z * vc.x + cf.w * vd.x;
                dst[1 * TILE] = cf.x * va.y + cf.y * vb.y + cf.z * vc.y + cf.w * vd.y;
                dst[2 * TILE] = cf.x * va.z + cf.y * vb.z + cf.z * vc.z + cf.w * vd.z;
                dst[3 * TILE] = cf.x * va.w + cf.y * vb.w + cf.z * vc.w + cf.w * vd.w;
                va = A[1]; vb = Bp[1]; vc = Cp[1]; vd = Dp[1];
                dst[4 * TILE] = cf.x * va.x + cf.y * vb.x + cf.z * vc.x + cf.w * vd.x;
                dst[5 * TILE] = cf.x * va.y + cf.y * vb.y + cf.z * vc.y + cf.w * vd.y;
                dst[6 * TILE] = cf.x * va.z + cf.y * vb.z + cf.z * vc.z + cf.w * vd.z;
                dst[7 * TILE] = cf.x * va.w + cf.y * vb.w + cf.z * vc.w + cf.w * vd.w;
            }
        }
        __syncthreads();

        // ---- GEMM step: acc[o][px] += w[o][c] * cols[c][px], c = 0..63 ----
        {
            const ulonglong2* cols16 = (const ulonglong2*)cols;
#pragma unroll 2
            for (int rg = 0; rg < 8; rg++) {
                const ulonglong2* cA = cols16 + rg * 8 * 32 + (tx ^ rg);
                const float4* wp = (const float4*)(wsm + (rg * 8) * CO_ + ty * 8);
#pragma unroll
                for (int j = 0; j < 8; j++) {
                    ulonglong2 a   = cA[0];    // pixels 4tx..4tx+3
                    ulonglong2 bq  = cA[16];   // pixels 64+4tx..+3
                    float4 wA = wp[0];         // weights o = ty*8 + 0..3 (broadcast LDS)
                    float4 wB = wp[1];         // weights o = ty*8 + 4..7
                    unsigned long long s;
                    s = splat2(wA.x);
                    fma2(acc[ 0], s, a.x); fma2(acc[ 1], s, a.y);
                    fma2(acc[ 2], s, bq.x); fma2(acc[ 3], s, bq.y);
                    s = splat2(wA.y);
                    fma2(acc[ 4], s, a.x); fma2(acc[ 5], s, a.y);
                    fma2(acc[ 6], s, bq.x); fma2(acc[ 7], s, bq.y);
                    s = splat2(wA.z);
                    fma2(acc[ 8], s, a.x); fma2(acc[ 9], s, a.y);
                    fma2(acc[10], s, bq.x); fma2(acc[11], s, bq.y);
                    s = splat2(wA.w);
                    fma2(acc[12], s, a.x); fma2(acc[13], s, a.y);
                    fma2(acc[14], s, bq.x); fma2(acc[15], s, bq.y);
                    s = splat2(wB.x);
                    fma2(acc[16], s, a.x); fma2(acc[17], s, a.y);
                    fma2(acc[18], s, bq.x); fma2(acc[19], s, bq.y);
                    s = splat2(wB.y);
                    fma2(acc[20], s, a.x); fma2(acc[21], s, a.y);
                    fma2(acc[22], s, bq.x); fma2(acc[23], s, bq.y);
                    s = splat2(wB.z);
                    fma2(acc[24], s, a.x); fma2(acc[25], s, a.y);
                    fma2(acc[26], s, bq.x); fma2(acc[27], s, bq.y);
                    s = splat2(wB.w);
                    fma2(acc[28], s, a.x); fma2(acc[29], s, a.y);
                    fma2(acc[30], s, bq.x); fma2(acc[31], s, bq.y);
                    cA += 32;    // next channel row of cols (128 floats)
                    wp += 16;    // next channel row of wsm  (64 floats)
                }
            }
        }
    }

    // ---- epilogue: float4 stores, coalesced along pixel dim ----
#pragma unroll
    for (int oi = 0; oi < 8; oi++) {
        int o = ty * 8 + oi;
        float* obase = out + ((size_t)(b * CO_ + o)) * NPIX + tile_base;
        float4 vA, vB;
        unpack2(acc[oi * 4 + 0], vA.x, vA.y);
        unpack2(acc[oi * 4 + 1], vA.z, vA.w);
        unpack2(acc[oi * 4 + 2], vB.x, vB.y);
        unpack2(acc[oi * 4 + 3], vB.z, vB.w);
        *(float4*)(obase + tx * 4)      = vA;
        *(float4*)(obase + 64 + tx * 4) = vB;
    }
}

extern "C" void kernel_launch(void* const* d_in, const int* in_sizes, int n_in,
                              void* d_out, int out_size) {
    const float* x   = (const float*)d_in[0];   // (8, 64, 96, 96)
    const float* off = (const float*)d_in[1];   // (8, 18, 96, 96)
    const float* w   = (const float*)d_in[2];   // (64, 64, 3, 3)
    float* out = (float*)d_out;                 // (8, 64, 96, 96)

    cudaFuncSetAttribute(dconv_kernel,
                         cudaFuncAttributeMaxDynamicSharedMemorySize, SMEM_BYTES);

    wtrans_kernel<<<(CO_ * C_ * K2_ + 255) / 256, 256>>>(w);

    dim3 tgrid(NPIX / 32, C_ / 32, B_);         // (288, 2, 8)
    xtrans_kernel<<<tgrid, 256>>>(x);

    dim3 grid(NPIX / TILE, B_);                 // (72, 8) = 576 blocks
    dconv_kernel<<<grid, NTHR, SMEM_BYTES>>>(off, out);
}

// round 11
// speedup vs baseline: 2.2125x; 1.0175x over previous
#include <cuda_runtime.h>

// DeformConv: B=8, C=64, H=W=96, COUT=64, 3x3, stride=1, pad=1, dil=1
// R11: f32x2 gather combine, 2 barriers/tap (coords double-buffered,
//      off[] loads hoisted over GEMM), cols prefetch in GEMM, fused prep.

#define B_    8
#define C_    64
#define H_    96
#define W_    96
#define CO_   64
#define K2_   9
#define NPIX  (H_ * W_)      // 9216
#define TILE  128            // output pixels per block
#define NTHR  128

// dynamic smem partition (bytes): cols 32768 + wsm 16384 + s_idx 2*1024 + s_cf 2*2048
#define SMEM_BYTES (32768 + 16384 + 2 * 1024 + 2 * 2048)   // 55296; x4 blocks = 216KB/SM

// [k][c][o] transposed weight (144 KB)
__device__ __align__(16) float g_w2[K2_ * C_ * CO_];
// [b][p][c] channel-last x  (18.9 MB)
__device__ __align__(16) float g_xT[B_ * NPIX * C_];

// fused prep: z = 0..7 -> x transpose slice for batch z; z == 8 -> weight transpose
__global__ void prep_kernel(const float* __restrict__ x, const float* __restrict__ w) {
    if (blockIdx.z == B_) {
        int idx = (blockIdx.y * gridDim.x + blockIdx.x) * 256 + threadIdx.x;
        if (idx < CO_ * C_ * K2_) {
            int o   = idx / (C_ * K2_);
            int rem = idx % (C_ * K2_);
            int c   = rem / K2_;
            int k   = rem % K2_;
            g_w2[(k * C_ + c) * CO_ + o] = w[idx];
        }
        return;
    }
    __shared__ float tl[32][33];
    int b  = blockIdx.z;
    int c0 = blockIdx.y * 32;
    int p0 = blockIdx.x * 32;
    int lane = threadIdx.x & 31;
    int wrp  = threadIdx.x >> 5;    // 0..7
#pragma unroll
    for (int i = 0; i < 4; i++) {
        int cr = wrp * 4 + i;
        tl[cr][lane] = x[((size_t)b * C_ + c0 + cr) * NPIX + p0 + lane];
    }
    __syncthreads();
#pragma unroll
    for (int i = 0; i < 4; i++) {
        int pr = wrp * 4 + i;
        g_xT[((size_t)b * NPIX + p0 + pr) * C_ + c0 + lane] = tl[lane][pr];
    }
}

// ---- f32x2 packed math ----
typedef unsigned long long ull;
__device__ __forceinline__ void fma2(ull& d, ull a, ull b) {
    asm("fma.rn.f32x2 %0, %1, %2, %0;" : "+l"(d) : "l"(a), "l"(b));
}
__device__ __forceinline__ void mul2(ull& d, ull a, ull b) {
    asm("mul.rn.f32x2 %0, %1, %2;" : "=l"(d) : "l"(a), "l"(b));
}
__device__ __forceinline__ ull pk2(float a, float b) {
    ull r; asm("mov.b64 %0, {%1, %2};" : "=l"(r) : "f"(a), "f"(b)); return r;
}
__device__ __forceinline__ ull splat2(float v) {
    ull r; asm("mov.b64 %0, {%1, %1};" : "=l"(r) : "f"(v)); return r;
}
__device__ __forceinline__ void unpack2(ull v, float& a, float& b) {
    asm("mov.b64 {%0, %1}, %2;" : "=f"(a), "=f"(b) : "l"(v));
}

// bilinear coord/coefficient fold for one pixel (verified R8/R9 math)
__device__ __forceinline__ void coord_fold(int ho, int wo, int k, float offy, float offx,
                                           int2& idx, float4& cfo) {
    float py  = (float)(ho - 1 + k / 3) + offy;
    float pxf = (float)(wo - 1 + k % 3) + offx;
    float y0f = floorf(py), x0f = floorf(pxf);
    float ly = py - y0f,    lx = pxf - x0f;
    int y0 = (int)y0f, x0 = (int)x0f;
    int y1 = y0 + 1,   x1 = x0 + 1;
    float vy0 = (y0 >= 0 && y0 < H_) ? 1.f : 0.f;
    float vy1 = (y1 >= 0 && y1 < H_) ? 1.f : 0.f;
    float vx0 = (x0 >= 0 && x0 < W_) ? 1.f : 0.f;
    float vx1 = (x1 >= 0 && x1 < W_) ? 1.f : 0.f;
    float w00 = (1.f - ly) * (1.f - lx) * vy0 * vx0;
    float w01 = (1.f - ly) * lx         * vy0 * vx1;
    float w10 = ly         * (1.f - lx) * vy1 * vx0;
    float w11 = ly         * lx         * vy1 * vx1;
    int xl = min(max(x0, 0), W_ - 2);
    float s0  = (x0 == xl)     ? 1.f : 0.f;
    float s1  = (x1 == xl)     ? 1.f : 0.f;
    float s0p = (x0 == xl + 1) ? 1.f : 0.f;
    float ca = s0  * w00 + s1 * w01;
    float cb = s0p * w00 + s0 * w01;
    float cc = s0  * w10 + s1 * w11;
    float cd = s0p * w10 + s0 * w11;
    int y0c = min(max(y0, 0), H_ - 1);
    int y1c = min(max(y1, 0), H_ - 1);
    idx = make_int2((y0c * W_ + xl) * C_, (y1c * W_ + xl) * C_);
    cfo = make_float4(ca, cb, cc, cd);
}

__global__ __launch_bounds__(NTHR, 4) void dconv_kernel(
    const float* __restrict__ off,
    float* __restrict__ out)
{
    extern __shared__ __align__(16) char smraw[];
    float*  cols  = (float*)smraw;                       // [C_ * TILE], XOR-swizzled
    float*  wsm   = cols + C_ * TILE;                    // [C_ * CO_]
    int2*   s_idx = (int2*)(wsm + C_ * CO_);             // [2][TILE]
    float4* s_cf  = (float4*)(s_idx + 2 * TILE);         // [2][TILE]

    const int t = threadIdx.x;
    const int b = blockIdx.y;
    const int tile_base = blockIdx.x * TILE;

    const int tx = t & 15;            // GEMM: pixels {4tx..} and {64+4tx..}
    const int ty = t >> 4;            // GEMM: outputs ty*8..+7
    const int sthr = t & 7;           // gather: channel group c = sthr*8..+7
    const int pg   = t >> 3;          // gather: pixel group base

    const int p  = tile_base + t;
    const int ho = p / W_;
    const int wo = p - ho * W_;
    const float* offb = off + (size_t)b * (2 * K2_) * NPIX + p;

    ull acc[32];
#pragma unroll
    for (int i = 0; i < 32; i++) acc[i] = 0ull;

    const float* xb = g_xT + (size_t)b * (NPIX * C_);

    // ---- prologue: coords for tap 0 ----
    {
        int2 ii; float4 cc4;
        coord_fold(ho, wo, 0, offb[0], offb[(size_t)NPIX], ii, cc4);
        s_idx[t] = ii;  s_cf[t] = cc4;
    }
    __syncthreads();

    for (int k = 0; k < K2_; k++) {
        const int kb = k & 1;

        // ---- stage weight tap slice into smem (16 KB, coalesced) ----
        {
            const float4* src = (const float4*)(g_w2 + k * (C_ * CO_));
            float4* dst4 = (float4*)wsm;
#pragma unroll
            for (int i = 0; i < 8; i++)
                dst4[t + NTHR * i] = __ldg(src + t + NTHR * i);
        }

        // ---- gather: coalesced LDG.128 + f32x2 bilinear combine ----
        {
            const int c0  = sthr * 8;
            const int swx = sthr * 4;
            const int2*   sip = s_idx + kb * TILE;
            const float4* scp = s_cf  + kb * TILE;
#pragma unroll 2
            for (int i = 0; i < 8; i++) {
                int pxi = pg + i * 16;
                int2   oo = sip[pxi];
                float4 cf = scp[pxi];
                ull cfx = splat2(cf.x), cfy = splat2(cf.y);
                ull cfz = splat2(cf.z), cfw = splat2(cf.w);
                const float4* A  = (const float4*)(xb + oo.x + c0);       // (y0, xl)
                const float4* Bp = (const float4*)(xb + oo.x + C_ + c0);  // (y0, xl+1)
                const float4* Cp = (const float4*)(xb + oo.y + c0);       // (y1, xl)
                const float4* Dp = (const float4*)(xb + oo.y + C_ + c0);  // (y1, xl+1)
                float* dst = &cols[c0 * TILE + (pxi ^ swx)];
#pragma unroll
                for (int h = 0; h < 2; h++) {
                    float4 va = A[h], vb = Bp[h], vc = Cp[h], vd = Dp[h];
                    ull r01, r23;
                    mul2(r01, cfx, pk2(va.x, va.y));
                    fma2(r01, cfy, pk2(vb.x, vb.y));
                    fma2(r01, cfz, pk2(vc.x, vc.y));
                    fma2(r01, cfw, pk2(vd.x, vd.y));
                    mul2(r23, cfx, pk2(va.z, va.w));
                    fma2(r23, cfy, pk2(vb.z, vb.w));
                    fma2(r23, cfz, pk2(vc.z, vc.w));
                    fma2(r23, cfw, pk2(vd.z, vd.w));
                    float f0, f1, f2, f3;
                    unpack2(r01, f0, f1);
                    unpack2(r23, f2, f3);
                    dst[(4 * h + 0) * TILE] = f0;
                    dst[(4 * h + 1) * TILE] = f1;
                    dst[(4 * h + 2) * TILE] = f2;
                    dst[(4 * h + 3) * TILE] = f3;
                }
            }
        }
        __syncthreads();   // gather done; coord buffer kb free; wsm/cols ready

        // ---- issue next tap's offset loads BEFORE the GEMM (latency hides) ----
        float offy_n = 0.f, offx_n = 0.f;
        if (k + 1 < K2_) {
            offy_n = __ldg(offb + (size_t)(2 * (k + 1)    ) * NPIX);
            offx_n = __ldg(offb + (size_t)(2 * (k + 1) + 1) * NPIX);
        }

        // ---- GEMM step: acc[o][px] += w[o][c] * cols[c][px], c = 0..63 ----
        {
            const ulonglong2* cols16 = (const ulonglong2*)cols;
#pragma unroll 2
            for (int rg = 0; rg < 8; rg++) {
                const ulonglong2* cA = cols16 + rg * 8 * 32 + (tx ^ rg);
                const float4* wp = (const float4*)(wsm + (rg * 8) * CO_ + ty * 8);
                ulonglong2 a  = cA[0];
                ulonglong2 bq = cA[16];
#pragma unroll
                for (int j = 0; j < 8; j++) {
                    ulonglong2 a_n, bq_n;
                    if (j < 7) { a_n = cA[32]; bq_n = cA[48]; }   // prefetch next channel
                    float4 wA = wp[0];         // broadcast LDS
                    float4 wB = wp[1];
                    ull s;
                    s = splat2(wA.x);
                    fma2(acc[ 0], s, a.x);  fma2(acc[ 1], s, a.y);
                    fma2(acc[ 2], s, bq.x); fma2(acc[ 3], s, bq.y);
                    s = splat2(wA.y);
                    fma2(acc[ 4], s, a.x);  fma2(acc[ 5], s, a.y);
                    fma2(acc[ 6], s, bq.x); fma2(acc[ 7], s, bq.y);
                    s = splat2(wA.z);
                    fma2(acc[ 8], s, a.x);  fma2(acc[ 9], s, a.y);
                    fma2(acc[10], s, bq.x); fma2(acc[11], s, bq.y);
                    s = splat2(wA.w);
                    fma2(acc[12], s, a.x);  fma2(acc[13], s, a.y);
                    fma2(acc[14], s, bq.x); fma2(acc[15], s, bq.y);
                    s = splat2(wB.x);
                    fma2(acc[16], s, a.x);  fma2(acc[17], s, a.y);
                    fma2(acc[18], s, bq.x); fma2(acc[19], s, bq.y);
                    s = splat2(wB.y);
                    fma2(acc[20], s, a.x);  fma2(acc[21], s, a.y);
                    fma2(acc[22], s, bq.x); fma2(acc[23], s, bq.y);
                    s = splat2(wB.z);
                    fma2(acc[24], s, a.x);  fma2(acc[25], s, a.y);
                    fma2(acc[26], s, bq.x); fma2(acc[27], s, bq.y);
                    s = splat2(wB.w);
                    fma2(acc[28], s, a.x);  fma2(acc[29], s, a.y);
                    fma2(acc[30], s, bq.x); fma2(acc[31], s, bq.y);
                    a = a_n; bq = bq_n;
                    cA += 32;    // next channel row of cols (128 floats)
                    wp += 16;    // next channel row of wsm  (64 floats)
                }
            }
        }

        // ---- finish next tap's coords (writes opposite buffer) ----
        if (k + 1 < K2_) {
            int2 ii; float4 cc4;
            coord_fold(ho, wo, k + 1, offy_n, offx_n, ii, cc4);
            s_idx[(1 - kb) * TILE + t] = ii;
            s_cf [(1 - kb) * TILE + t] = cc4;
        }
        __syncthreads();   // GEMM done reading cols/wsm; next coords visible
    }

    // ---- epilogue: float4 stores, coalesced along pixel dim ----
#pragma unroll
    for (int oi = 0; oi < 8; oi++) {
        int o = ty * 8 + oi;
        float* obase = out + ((size_t)(b * CO_ + o)) * NPIX + tile_base;
        float4 vA, vB;
        unpack2(acc[oi * 4 + 0], vA.x, vA.y);
        unpack2(acc[oi * 4 + 1], vA.z, vA.w);
        unpack2(acc[oi * 4 + 2], vB.x, vB.y);
        unpack2(acc[oi * 4 + 3], vB.z, vB.w);
        *(float4*)(obase + tx * 4)      = vA;
        *(float4*)(obase + 64 + tx * 4) = vB;
    }
}

extern "C" void kernel_launch(void* const* d_in, const int* in_sizes, int n_in,
                              void* d_out, int out_size) {
    const float* x   = (const float*)d_in[0];   // (8, 64, 96, 96)
    const float* off = (const float*)d_in[1];   // (8, 18, 96, 96)
    const float* w   = (const float*)d_in[2];   // (64, 64, 3, 3)
    float* out = (float*)d_out;                 // (8, 64, 96, 96)

    cudaFuncSetAttribute(dconv_kernel,
                         cudaFuncAttributeMaxDynamicSharedMemorySize, SMEM_BYTES);

    dim3 pgrid(NPIX / 32, C_ / 32, B_ + 1);     // (288, 2, 9): z<8 xtrans, z==8 wtrans
    prep_kernel<<<pgrid, 256>>>(x, w);

    dim3 grid(NPIX / TILE, B_);                 // (72, 8) = 576 blocks
    dconv_kernel<<<grid, NTHR, SMEM_BYTES>>>(off, out);
}

// round 13
// speedup vs baseline: 3.2790x; 1.4820x over previous
#include <cuda_runtime.h>
#include <cuda_bf16.h>
#include <cstdint>

// DeformConv: B=8, C=64, H=W=96, COUT=64, 3x3, s=1, p=1, d=1
// R13: warp-level mma.sync bf16 (3-term hi/lo split) — portable PTX that
//      compiles for compute_103 (no tcgen05). Per block: 128px x 64o x 64c
//      per tap, accumulated in registers across 9 taps. 4 blocks/SM, 1 wave.

#define B_    8
#define C_    64
#define H_    96
#define W_    96
#define CO_   64
#define K2_   9
#define NPIX  (H_ * W_)      // 9216
#define TILE  128
#define NTHR  256

// smem layout (bytes)
#define OFF_SIDX 0                    // int2[128]   = 1024
#define OFF_SCF  1024                 // float4[128] = 2048
#define OFF_AH   4096                 // 128*64 bf16 swizzled = 16384
#define OFF_AL   (4096 + 16384)
#define OFF_BH   (4096 + 32768)      // 64 * 72 bf16 = 9216
#define OFF_BL   (OFF_BH + 9216)
#define SMEM_BYTES (OFF_BL + 9216)   // 55296 -> 4 blocks/SM

#define BSTR 72                       // staged W row stride in bf16 (36 u32)

// [b][p][c] channel-last x (fp32, 18.9 MB)
__device__ __align__(16) float g_xT[B_ * NPIX * C_];
// [k][o][c] split weights, bf16 (72 KB each)
__device__ __align__(16) __nv_bfloat16 g_wbh[K2_ * CO_ * C_];
__device__ __align__(16) __nv_bfloat16 g_wbl[K2_ * CO_ * C_];

// fused prep: z = 0..7 -> x transpose slice; z == 8 -> weight hi/lo split
__global__ void prep_kernel(const float* __restrict__ x, const float* __restrict__ w) {
    if (blockIdx.z == B_) {
        int idx = (blockIdx.y * gridDim.x + blockIdx.x) * 256 + threadIdx.x;
        if (idx < CO_ * C_ * K2_) {
            int o   = idx / (C_ * K2_);
            int rem = idx % (C_ * K2_);
            int c   = rem / K2_;
            int k   = rem % K2_;
            float v = w[idx];
            __nv_bfloat16 hi = __float2bfloat16_rn(v);
            float lo = v - __bfloat162float(hi);
            g_wbh[(k * CO_ + o) * C_ + c] = hi;
            g_wbl[(k * CO_ + o) * C_ + c] = __float2bfloat16_rn(lo);
        }
        return;
    }
    __shared__ float tl[32][33];
    int b  = blockIdx.z;
    int c0 = blockIdx.y * 32;
    int p0 = blockIdx.x * 32;
    int lane = threadIdx.x & 31;
    int wrp  = threadIdx.x >> 5;
#pragma unroll
    for (int i = 0; i < 4; i++) {
        int cr = wrp * 4 + i;
        tl[cr][lane] = x[((size_t)b * C_ + c0 + cr) * NPIX + p0 + lane];
    }
    __syncthreads();
#pragma unroll
    for (int i = 0; i < 4; i++) {
        int pr = wrp * 4 + i;
        g_xT[((size_t)b * NPIX + p0 + pr) * C_ + c0 + lane] = tl[lane][pr];
    }
}

// ---- helpers ----
typedef unsigned long long ull;
__device__ __forceinline__ void fma2(ull& d, ull a, ull b) {
    asm("fma.rn.f32x2 %0, %1, %2, %0;" : "+l"(d) : "l"(a), "l"(b));
}
__device__ __forceinline__ void mul2(ull& d, ull a, ull b) {
    asm("mul.rn.f32x2 %0, %1, %2;" : "=l"(d) : "l"(a), "l"(b));
}
__device__ __forceinline__ ull pk2(float a, float b) {
    ull r; asm("mov.b64 %0, {%1, %2};" : "=l"(r) : "f"(a), "f"(b)); return r;
}
__device__ __forceinline__ ull splat2(float v) {
    ull r; asm("mov.b64 %0, {%1, %1};" : "=l"(r) : "f"(v)); return r;
}
__device__ __forceinline__ void unpack2(ull v, float& a, float& b) {
    asm("mov.b64 {%0, %1}, %2;" : "=f"(a), "=f"(b) : "l"(v));
}
// packed bf16x2: high half = bf16(hi_val), low half = bf16(lo_val)
__device__ __forceinline__ uint32_t bf2(float hi_val, float lo_val) {
    uint32_t r;
    asm("cvt.rn.bf16x2.f32 %0, %1, %2;" : "=r"(r) : "f"(hi_val), "f"(lo_val));
    return r;
}
__device__ __forceinline__ uint32_t smem_u32(const void* p) {
    uint32_t a;
    asm("{ .reg .u64 t; cvta.to.shared.u64 t, %1; cvt.u32.u64 %0, t; }" : "=r"(a) : "l"(p));
    return a;
}
__device__ __forceinline__ uint32_t swz(uint32_t off) {      // SW128
    return off ^ ((off >> 3) & 0x70);
}
__device__ __forceinline__ void ldm4(uint32_t* r, uint32_t addr) {
    asm volatile("ldmatrix.sync.aligned.m8n8.x4.shared.b16 {%0,%1,%2,%3}, [%4];"
                 : "=r"(r[0]), "=r"(r[1]), "=r"(r[2]), "=r"(r[3]) : "r"(addr));
}
__device__ __forceinline__ void mma_bf16(float* d, const uint32_t* a, uint32_t b0, uint32_t b1) {
    asm volatile(
        "mma.sync.aligned.m16n8k16.row.col.f32.bf16.bf16.f32 "
        "{%0,%1,%2,%3}, {%4,%5,%6,%7}, {%8,%9}, {%0,%1,%2,%3};"
        : "+f"(d[0]), "+f"(d[1]), "+f"(d[2]), "+f"(d[3])
        : "r"(a[0]), "r"(a[1]), "r"(a[2]), "r"(a[3]), "r"(b0), "r"(b1));
}

// verified bilinear coord/coefficient fold (x-corner folded into row pair)
__device__ __forceinline__ void coord_fold(int ho, int wo, int k, float offy, float offx,
                                           int2& idx, float4& cfo) {
    float py  = (float)(ho - 1 + k / 3) + offy;
    float pxf = (float)(wo - 1 + k % 3) + offx;
    float y0f = floorf(py), x0f = floorf(pxf);
    float ly = py - y0f,    lx = pxf - x0f;
    int y0 = (int)y0f, x0 = (int)x0f;
    int y1 = y0 + 1,   x1 = x0 + 1;
    float vy0 = (y0 >= 0 && y0 < H_) ? 1.f : 0.f;
    float vy1 = (y1 >= 0 && y1 < H_) ? 1.f : 0.f;
    float vx0 = (x0 >= 0 && x0 < W_) ? 1.f : 0.f;
    float vx1 = (x1 >= 0 && x1 < W_) ? 1.f : 0.f;
    float w00 = (1.f - ly) * (1.f - lx) * vy0 * vx0;
    float w01 = (1.f - ly) * lx         * vy0 * vx1;
    float w10 = ly         * (1.f - lx) * vy1 * vx0;
    float w11 = ly         * lx         * vy1 * vx1;
    int xl = min(max(x0, 0), W_ - 2);
    float s0  = (x0 == xl)     ? 1.f : 0.f;
    float s1  = (x1 == xl)     ? 1.f : 0.f;
    float s0p = (x0 == xl + 1) ? 1.f : 0.f;
    float ca = s0  * w00 + s1 * w01;
    float cb = s0p * w00 + s0 * w01;
    float cc = s0  * w10 + s1 * w11;
    float cd = s0p * w10 + s0 * w11;
    int y0c = min(max(y0, 0), H_ - 1);
    int y1c = min(max(y1, 0), H_ - 1);
    idx = make_int2((y0c * W_ + xl) * C_, (y1c * W_ + xl) * C_);
    cfo = make_float4(ca, cb, cc, cd);
}

__global__ __launch_bounds__(NTHR, 4) void dconv_kernel(
    const float* __restrict__ off,
    float* __restrict__ out)
{
    extern __shared__ __align__(1024) char smraw[];
    const uint32_t smb = smem_u32(smraw);
    int2*   s_idx = (int2*)(smraw + OFF_SIDX);
    float4* s_cf  = (float4*)(smraw + OFF_SCF);

    const int t    = threadIdx.x;
    const int lane = t & 31;
    const int wrp  = t >> 5;
    const int b    = blockIdx.y;
    const int tile_base = blockIdx.x * TILE;

    // gather mapping: 16 channel-groups (4 ch) x 16 pixel-groups
    const int sthr = t & 15;
    const int pg   = t >> 4;

    // A-fragment ldmatrix lane address components
    const int seg  = lane >> 3;                       // 0..3 -> (a0,a1,a2,a3) tiles
    const int arow = wrp * 16 + (lane & 7) + (seg & 1) * 8;
    const int acol = (seg >> 1) * 16;                 // byte offset within row

    // B-fragment LDS components (u32 view of staged W, stride 36 u32)
    const int bo = lane >> 2;                         // n within 8-tile
    const int bc = lane & 3;                          // k-pair

    int ho = 0, wo = 0;
    if (t < TILE) { int p = tile_base + t; ho = p / W_; wo = p - ho * W_; }
    const float* offb = off + (size_t)b * (2 * K2_) * NPIX + tile_base + t;

    float acc[8][4];
#pragma unroll
    for (int n = 0; n < 8; n++)
#pragma unroll
        for (int i = 0; i < 4; i++) acc[n][i] = 0.f;

    const float* xb = g_xT + (size_t)b * (NPIX * C_);

    for (int k = 0; k < K2_; k++) {
        __syncthreads();   // prev MMA done reading A/B smem

        // ---- per-pixel coords (t < 128) ----
        if (t < TILE) {
            float offy = __ldg(offb + (size_t)(2 * k    ) * NPIX);
            float offx = __ldg(offb + (size_t)(2 * k + 1) * NPIX);
            int2 ii; float4 cc4;
            coord_fold(ho, wo, k, offy, offx, ii, cc4);
            s_idx[t] = ii;  s_cf[t] = cc4;
        }

        // ---- stage split weights: [o][c] bf16, stride 72 (36 u32) ----
        {
            const uint32_t* wh = (const uint32_t*)(g_wbh + (size_t)k * CO_ * C_);
            const uint32_t* wl = (const uint32_t*)(g_wbl + (size_t)k * CO_ * C_);
            uint32_t* bh = (uint32_t*)(smraw + OFF_BH);
            uint32_t* bl = (uint32_t*)(smraw + OFF_BL);
#pragma unroll
            for (int rep = 0; rep < 8; rep++) {
                int idx = t + rep * NTHR;             // 0..2047
                int o = idx >> 5, cp = idx & 31;
                bh[o * 36 + cp] = __ldg(wh + idx);
                bl[o * 36 + cp] = __ldg(wl + idx);
            }
        }
        __syncthreads();   // coords visible

        // ---- gather -> split bf16 A tiles (coalesced LDG.128, f32x2 combine) ----
        {
            const int c0 = sthr * 4;
            char* ahb = smraw + OFF_AH;
            char* alb = smraw + OFF_AL;
#pragma unroll 2
            for (int i = 0; i < 8; i++) {
                int pxi = pg + i * 16;
                int2   oo = s_idx[pxi];
                float4 cf = s_cf[pxi];
                float4 va = *(const float4*)(xb + oo.x + c0);
                float4 vb = *(const float4*)(xb + oo.x + C_ + c0);
                float4 vc = *(const float4*)(xb + oo.y + c0);
                float4 vd = *(const float4*)(xb + oo.y + C_ + c0);
                ull r01, r23;
                mul2(r01, splat2(cf.x), pk2(va.x, va.y));
                fma2(r01, splat2(cf.y), pk2(vb.x, vb.y));
                fma2(r01, splat2(cf.z), pk2(vc.x, vc.y));
                fma2(r01, splat2(cf.w), pk2(vd.x, vd.y));
                mul2(r23, splat2(cf.x), pk2(va.z, va.w));
                fma2(r23, splat2(cf.y), pk2(vb.z, vb.w));
                fma2(r23, splat2(cf.z), pk2(vc.z, vc.w));
                fma2(r23, splat2(cf.w), pk2(vd.z, vd.w));
                float f0, f1, f2, f3;
                unpack2(r01, f0, f1);
                unpack2(r23, f2, f3);
                uint32_t h01 = bf2(f1, f0);
                uint32_t h23 = bf2(f3, f2);
                float hf0 = __uint_as_float(h01 << 16);
                float hf1 = __uint_as_float(h01 & 0xFFFF0000u);
                float hf2 = __uint_as_float(h23 << 16);
                float hf3 = __uint_as_float(h23 & 0xFFFF0000u);
                uint32_t l01 = bf2(f1 - hf1, f0 - hf0);
                uint32_t l23 = bf2(f3 - hf3, f2 - hf2);
                uint32_t so = swz((uint32_t)pxi * 128 + c0 * 2);
                *(ull*)(ahb + so) = (ull)h01 | ((ull)h23 << 32);
                *(ull*)(alb + so) = (ull)l01 | ((ull)l23 << 32);
            }
        }
        __syncthreads();   // A tiles + W stage ready

        // ---- MMA: D[16px x 64o] += A[16px x 64c] * W^T, 3-term split ----
        {
            const uint32_t* bhp = (const uint32_t*)(smraw + OFF_BH);
            const uint32_t* blp = (const uint32_t*)(smraw + OFF_BL);
            const int bthr = bo * 36 + bc;            // thread's base word in W stage
#pragma unroll
            for (int ks = 0; ks < 4; ks++) {
                uint32_t abyte = swz((uint32_t)arow * 128 + ks * 32 + acol);
                uint32_t ah[4], al[4];
                ldm4(ah, smb + OFF_AH + abyte);
                ldm4(al, smb + OFF_AL + abyte);
                const int kw = ks * 8 + bthr;
#pragma unroll
                for (int n = 0; n < 8; n++) {
                    int wi = n * (8 * 36) + kw;
                    uint32_t bh0 = bhp[wi], bh1 = bhp[wi + 4];
                    uint32_t bl0 = blp[wi], bl1 = blp[wi + 4];
                    mma_bf16(acc[n], ah, bh0, bh1);
                    mma_bf16(acc[n], al, bh0, bh1);
                    mma_bf16(acc[n], ah, bl0, bl1);
                }
            }
        }
    }

    // ---- epilogue: D fragment scatter (rows = px, cols = o) ----
    {
        const int g  = lane >> 2;
        const int tt = lane & 3;
        const int px0 = wrp * 16 + g;
        float* ob = out + ((size_t)b * CO_) * NPIX + tile_base;
#pragma unroll
        for (int n = 0; n < 8; n++) {
            int o = n * 8 + tt * 2;
            ob[(size_t)o       * NPIX + px0    ] = acc[n][0];
            ob[(size_t)(o + 1) * NPIX + px0    ] = acc[n][1];
            ob[(size_t)o       * NPIX + px0 + 8] = acc[n][2];
            ob[(size_t)(o + 1) * NPIX + px0 + 8] = acc[n][3];
        }
    }
}

extern "C" void kernel_launch(void* const* d_in, const int* in_sizes, int n_in,
                              void* d_out, int out_size) {
    const float* x   = (const float*)d_in[0];   // (8, 64, 96, 96)
    const float* off = (const float*)d_in[1];   // (8, 18, 96, 96)
    const float* w   = (const float*)d_in[2];   // (64, 64, 3, 3)
    float* out = (float*)d_out;                 // (8, 64, 96, 96)

    cudaFuncSetAttribute(dconv_kernel,
                         cudaFuncAttributeMaxDynamicSharedMemorySize, SMEM_BYTES);

    dim3 pgrid(NPIX / 32, C_ / 32, B_ + 1);     // (288, 2, 9)
    prep_kernel<<<pgrid, 256>>>(x, w);

    dim3 grid(NPIX / TILE, B_);                 // (72, 8) = 576 blocks
    dconv_kernel<<<grid, NTHR, SMEM_BYTES>>>(off, out);
}